// round 13
// baseline (speedup 1.0000x reference)
#include <cuda_runtime.h>
#include <math.h>

#define B_     2048
#define S_     96
#define F_     32
#define H_     256
#define O_     6
#define LA_    32
#define WARM_  96
#define STEPS_ 128
#define MB_    14
#define PAIRS_ 7
#define NTH_   512
#define NBLK_  147        // ceil(2048 / 14); grid MUST be <= 148 (one wave)
#define KTOT_  (F_ + H_)  // 288 combined k range (x rows 0..31, h rows 32..287)
#define KHALF_ 144        // symmetric split-k per warpgroup
#define KPAD_  296        // padded weight rows: linear prefetch never OOB
#define SSTRIDE_ 30       // floats per state row: 14 elems DUPLICATED (28) + 2 pad
#define SROWU_  (SSTRIDE_ / 2)   // 15 ull per state row

typedef unsigned long long ull;

// Static device scratch (no allocation allowed).
__device__ float4 g_W[KPAD_ * H_];   // [k][jh] -> (i,f,g,o); k<32 from Wih, 32..287 Whh
__device__ float4 g_bias[H_];        // combined bias (i,f,g,o)

// ---- packed fp32x2 helpers ----
__device__ __forceinline__ ull ffma2(ull a, ull b, ull c) {
    ull d;
    asm("fma.rn.f32x2 %0, %1, %2, %3;" : "=l"(d) : "l"(a), "l"(b), "l"(c));
    return d;
}
__device__ __forceinline__ ull add2(ull a, ull b) {
    ull d;
    asm("add.rn.f32x2 %0, %1, %2;" : "=l"(d) : "l"(a), "l"(b));
    return d;
}
__device__ __forceinline__ float2 unpk(ull v) {
    unsigned lo, hi;
    asm("mov.b64 {%0, %1}, %2;" : "=r"(lo), "=r"(hi) : "l"(v));
    return make_float2(__uint_as_float(lo), __uint_as_float(hi));
}
__device__ __forceinline__ ull pk(float a, float b) {
    ull d;
    asm("mov.b64 %0, {%1, %2};" : "=l"(d) : "r"(__float_as_uint(a)), "r"(__float_as_uint(b)));
    return d;
}
// ACCURATE activations (fast-math fails: STE chaos amplified ~1e-6 act err to 2.4e-3)
__device__ __forceinline__ float sigf(float x) { return 1.0f / (1.0f + expf(-x)); }

// One-time weight interleave: combined (x|h) k range, 4-gate float4, bias fold.
__global__ void pack_kernel(const float* __restrict__ Wih, const float* __restrict__ Whh,
                            const float* __restrict__ bih, const float* __restrict__ bhh) {
    int idx = blockIdx.x * blockDim.x + threadIdx.x;
    if (idx >= KPAD_ * H_) return;
    int k  = idx >> 8;
    int jh = idx & 255;
    float4 v = make_float4(0.f, 0.f, 0.f, 0.f);
    if (k < F_) {
        v.x = Wih[(0 * H_ + jh) * F_ + k];
        v.y = Wih[(1 * H_ + jh) * F_ + k];
        v.z = Wih[(2 * H_ + jh) * F_ + k];
        v.w = Wih[(3 * H_ + jh) * F_ + k];
    } else if (k < KTOT_) {
        int kk = k - F_;
        v.x = Whh[(0 * H_ + jh) * H_ + kk];
        v.y = Whh[(1 * H_ + jh) * H_ + kk];
        v.z = Whh[(2 * H_ + jh) * H_ + kk];
        v.w = Whh[(3 * H_ + jh) * H_ + kk];
    }
    g_W[idx] = v;
    if (k == 0) {
        float4 b;
        b.x = bih[0 * H_ + jh] + bhh[0 * H_ + jh];
        b.y = bih[1 * H_ + jh] + bhh[1 * H_ + jh];
        b.z = bih[2 * H_ + jh] + bhh[2 * H_ + jh];
        b.w = bih[3 * H_ + jh] + bhh[3 * H_ + jh];
        g_bias[jh] = b;
    }
}

// One k-slice, gate-paired lanes: for each of 14 batch elems, one LDS.64 of the
// DUPLICATED state value (v,v) feeds two FFMA2: lanes (i,f) with wif and (g,o)
// with wgo. 28 FFMA2 per k, ZERO splat MOVs (weights used straight from LDG.128).
__device__ __forceinline__ void gemm_body(const ull* __restrict__ row,
                                          ull wif, ull wgo,
                                          ull (&acc)[14][2]) {
#pragma unroll
    for (int e = 0; e < 14; e++) {
        ull h = row[e];
        acc[e][0] = ffma2(h, wif, acc[e][0]);
        acc[e][1] = ffma2(h, wgo, acc[e][1]);
    }
}

// KN even. R10's proven 2-deep weight prefetch, linear pointer increments.
// float4 weight reinterpreted as ulonglong2: .x = (wi,wf), .y = (wg,wo).
template <int KN>
__device__ __forceinline__ void gemm_part(const ulonglong2* __restrict__ Wcol,
                                          const ull* __restrict__ Sm,
                                          ull (&acc)[14][2]) {
    ulonglong2 wa = Wcol[0];
    ulonglong2 wb = Wcol[H_];
    const ulonglong2* Wq = Wcol + 2 * H_;
    const ull* Sr = Sm;
#pragma unroll 1
    for (int k = 0; k < KN; k += 2) {
        ulonglong2 n0 = Wq[0];
        ulonglong2 n1 = Wq[H_];
        gemm_body(Sr, wa.x, wa.y, acc);
        gemm_body(Sr + SROWU_, wb.x, wb.y, acc);
        wa = n0;
        wb = n1;
        Wq += 2 * H_;
        Sr += 2 * SROWU_;
    }
}

// Dynamic smem layout (floats):
//   S     [288][30]       : 8640 floats  (rows 0..31 = x_t dup, 32..287 = h dup)
//   Ex    [256][28] ull   : 14336 floats (split-k partial exchange / readout scratch)
//   WfcS  [6][256]        : 1536
//   bfcS  [8], oS [84+pad]
#define SM_S_    0
#define SM_EX_   (SM_S_ + KTOT_ * SSTRIDE_)
#define SM_WFC_  (SM_EX_ + 256 * 28 * 2)
#define SM_BFC_  (SM_WFC_ + O_ * H_)
#define SM_OS_   (SM_BFC_ + 8)
#define SM_TOTF_ (SM_OS_ + MB_ * O_ + 4)
#define SMEM_BYTES_ (SM_TOTF_ * 4)

__global__ void __launch_bounds__(NTH_, 1)
lstm_kernel(const float* __restrict__ x, const float* __restrict__ Wfc,
            const float* __restrict__ bfc, float* __restrict__ out) {
    extern __shared__ __align__(16) float smem[];
    float* S    = smem + SM_S_;
    ull*   Ex   = (ull*)(smem + SM_EX_);     // [jh][28]  (e*2 + gatepair)
    float* WfcS = smem + SM_WFC_;
    float* bfcS = smem + SM_BFC_;
    float* oS   = smem + SM_OS_;

    const int tid = threadIdx.x;
    const int jh  = tid & 255;
    const int wg  = tid >> 8;        // k-half: 0 -> k[0,144), 1 -> k[144,288)
    const int b0  = blockIdx.x * MB_;

    for (int i = tid; i < KTOT_ * SSTRIDE_; i += NTH_) S[i] = 0.0f;
    for (int i = tid; i < O_ * H_; i += NTH_) WfcS[i] = Wfc[i];
    if (tid < O_) bfcS[tid] = bfc[tid];

    // c state: wg0 owns elems 0..7; wg1 elems 8..13
    float c[8];
#pragma unroll
    for (int r = 0; r < 8; r++) c[r] = 0.0f;

    const int ebase = wg ? 8 : 0;
    const int nE    = wg ? 6 : 8;

    const float4 bias = g_bias[jh];
    const ulonglong2* __restrict__ Wcol =
        (const ulonglong2*)(g_W + (size_t)(wg * KHALF_) * H_ + jh);
    const ull* __restrict__ Sbase = (const ull*)(S + wg * KHALF_ * SSTRIDE_);

    float* Hrow  = S + (F_ + jh) * SSTRIDE_;
    ull*   ExRow = Ex + (size_t)jh * 28;

    // ---- x stager (wg0, as R10): thread slots (f, pair), 224 slots ----
    const bool stager = tid < F_ * PAIRS_;
    int xf = 0, xp = 0;
    const float* xr0 = x;
    const float* xr1 = x;
    float xa = 0.0f, xb = 0.0f;
    if (stager) {
        xf = tid / PAIRS_;
        xp = tid - xf * PAIRS_;
        int r0 = b0 + 2 * xp;     if (r0 > B_ - 1) r0 = B_ - 1;
        int r1 = b0 + 2 * xp + 1; if (r1 > B_ - 1) r1 = B_ - 1;
        xr0 = x + (size_t)r0 * S_ * F_ + xf;
        xr1 = x + (size_t)r1 * S_ * F_ + xf;
        xa = xr0[0];
        xb = xr1[0];
    }

    __syncthreads();

    for (int t = 0; t < STEPS_; t++) {
        const bool la = (t >= WARM_);

        // ---- stage x_t DUPLICATED into S rows 0..31 ----
        if (stager) {
            float v0 = xa, v1 = xb;
            if (la && xf < O_) {
                v0 = oS[(2 * xp) * O_ + xf];
                v1 = oS[(2 * xp + 1) * O_ + xf];
            }
            float* xrow = S + xf * SSTRIDE_;
            *(ull*)(xrow + 4 * xp)     = pk(v0, v0);
            *(ull*)(xrow + 4 * xp + 2) = pk(v1, v1);
            int tn = t + 1;
            if (tn < STEPS_) {
                int tsn = (tn < WARM_) ? tn : (tn - WARM_);
                xa = xr0[(size_t)tsn * F_];
                xb = xr1[(size_t)tsn * F_];
            }
        }
        __syncthreads();   // x rows ready; h rows stable

        // ---- split-k gate-paired GEMM over this WG's 144 k-slices ----
        ull acc[14][2];
        if (wg == 0) {
            ull bif = pk(bias.x, bias.y);
            ull bgo = pk(bias.z, bias.w);
#pragma unroll
            for (int e = 0; e < 14; e++) { acc[e][0] = bif; acc[e][1] = bgo; }
        } else {
            ull z = pk(0.0f, 0.0f);
#pragma unroll
            for (int e = 0; e < 14; e++) { acc[e][0] = z; acc[e][1] = z; }
        }
        gemm_part<KHALF_>(Wcol, Sbase, acc);

        // ---- exchange complement k-half partials (by batch elem) ----
        if (wg == 0) {            // give elems 8..13 to wg1
#pragma unroll
            for (int e = 8; e < 14; e++) {
                ExRow[2 * e]     = acc[e][0];
                ExRow[2 * e + 1] = acc[e][1];
            }
        } else {                  // give elems 0..7 to wg0
#pragma unroll
            for (int e = 0; e < 8; e++) {
                ExRow[2 * e]     = acc[e][0];
                ExRow[2 * e + 1] = acc[e][1];
            }
        }
        __syncthreads();   // partials visible; all S reads complete

        // ---- reduce own elems + elementwise cell + write new h (duplicated) ----
#pragma unroll
        for (int q = 0; q < 8; q++) {
            if (q >= nE) break;
            int e = ebase + q;
            float2 g_if = unpk(add2(acc[e][0], ExRow[2 * e]));      // (i, f)
            float2 g_go = unpk(add2(acc[e][1], ExRow[2 * e + 1]));  // (g, o)
            float c0 = sigf(g_if.y) * c[q] + sigf(g_if.x) * tanhf(g_go.x);
            c[q] = c0;
            float h = sigf(g_go.y) * tanhf(c0);
            *(ull*)(Hrow + 2 * e) = pk(h, h);
        }
        __syncthreads();   // new h complete

        // ---- STE readout: out = (h>0) @ W_fc^T + b_fc  (t = 95..127) ----
        if (t >= WARM_ - 1) {
            float* red = (float*)Ex;   // scratch [84][4] (Ex dead until next exchange)
            const float* Hs = S + F_ * SSTRIDE_;
            if (tid < MB_ * O_ * 4) {
                int slot  = tid >> 2;
                int chunk = tid & 3;
                int r  = slot / O_;
                int oi = slot - r * O_;
                const float* wrow = WfcS + oi * H_;
                float s0 = 0.0f, s1 = 0.0f;
                int jb = chunk * 64;
#pragma unroll 8
                for (int j = 0; j < 64; j += 2) {
                    s0 += (Hs[(jb + j) * SSTRIDE_ + 2 * r] > 0.0f)     ? wrow[jb + j]     : 0.0f;
                    s1 += (Hs[(jb + j + 1) * SSTRIDE_ + 2 * r] > 0.0f) ? wrow[jb + j + 1] : 0.0f;
                }
                red[slot * 4 + chunk] = s0 + s1;
            }
            __syncthreads();
            if (tid < MB_ * O_) {
                int r  = tid / O_;
                int oi = tid - r * O_;
                float a = bfcS[oi] + red[tid * 4 + 0] + red[tid * 4 + 1]
                                   + red[tid * 4 + 2] + red[tid * 4 + 3];
                oS[tid] = a;
                if (b0 + r < B_)
                    out[((size_t)(b0 + r) * (LA_ + 1) + (t - (WARM_ - 1))) * O_ + oi] = a;
            }
            __syncthreads();   // oS ready; red scratch dead before next exchange
        }
    }
}

extern "C" void kernel_launch(void* const* d_in, const int* in_sizes, int n_in,
                              void* d_out, int out_size) {
    const float* x    = (const float*)d_in[0];
    const float* W_ih = (const float*)d_in[1];
    const float* W_hh = (const float*)d_in[2];
    const float* b_ih = (const float*)d_in[3];
    const float* b_hh = (const float*)d_in[4];
    const float* W_fc = (const float*)d_in[5];
    const float* b_fc = (const float*)d_in[6];
    float* out = (float*)d_out;

    cudaFuncSetAttribute(lstm_kernel, cudaFuncAttributeMaxDynamicSharedMemorySize,
                         SMEM_BYTES_);

    pack_kernel<<<(KPAD_ * H_ + 255) / 256, 256>>>(W_ih, W_hh, b_ih, b_hh);
    lstm_kernel<<<NBLK_, NTH_, SMEM_BYTES_>>>(x, W_fc, b_fc, out);
}

// round 14
// speedup vs baseline: 1.3108x; 1.3108x over previous
#include <cuda_runtime.h>
#include <math.h>

#define B_     2048
#define S_     96
#define F_     32
#define H_     256
#define O_     6
#define LA_    32
#define WARM_  96
#define STEPS_ 128
#define MB_    14
#define PAIRS_ 7
#define NTH_   512
#define NBLK_  147        // ceil(2048 / 14); grid MUST be <= 148 (one wave)
#define KTOT_  (F_ + H_)  // 288 combined k range
#define KHALF_ 144        // symmetric split-k per warpgroup
#define KPAD_  296        // padded weight rows: linear prefetch never OOB
#define HSTRIDE_ 18       // floats per state row: 14 data + 4 pad, 8B-aligned rows
                          // (LDS.64 only — .128 quads + 28 accs @128-reg cap => MOV blowup)

typedef unsigned long long ull;

// Static device scratch (no allocation allowed).
__device__ float4 g_W[KPAD_ * H_];   // [k][jh] -> (i,f,g,o); k<32 from Wih, 32..287 Whh
__device__ float4 g_bias[H_];        // combined bias (i,f,g,o)

// ---- packed fp32x2 helpers ----
__device__ __forceinline__ ull ffma2(ull a, ull b, ull c) {
    ull d;
    asm("fma.rn.f32x2 %0, %1, %2, %3;" : "=l"(d) : "l"(a), "l"(b), "l"(c));
    return d;
}
__device__ __forceinline__ ull add2(ull a, ull b) {
    ull d;
    asm("add.rn.f32x2 %0, %1, %2;" : "=l"(d) : "l"(a), "l"(b));
    return d;
}
__device__ __forceinline__ ull splat2(float x) {
    ull d; unsigned u = __float_as_uint(x);
    asm("mov.b64 %0, {%1, %1};" : "=l"(d) : "r"(u));
    return d;
}
__device__ __forceinline__ float2 unpk(ull v) {
    unsigned lo, hi;
    asm("mov.b64 {%0, %1}, %2;" : "=r"(lo), "=r"(hi) : "l"(v));
    return make_float2(__uint_as_float(lo), __uint_as_float(hi));
}
__device__ __forceinline__ ull pk(float a, float b) {
    ull d;
    asm("mov.b64 %0, {%1, %2};" : "=l"(d) : "r"(__float_as_uint(a)), "r"(__float_as_uint(b)));
    return d;
}
// ACCURATE activations (fast-math fails: STE chaos amplified ~1e-6 act err to 2.4e-3)
__device__ __forceinline__ float sigf(float x) { return 1.0f / (1.0f + expf(-x)); }

// One-time weight interleave: combined (x|h) k range, 4-gate float4, bias fold.
__global__ void pack_kernel(const float* __restrict__ Wih, const float* __restrict__ Whh,
                            const float* __restrict__ bih, const float* __restrict__ bhh) {
    int idx = blockIdx.x * blockDim.x + threadIdx.x;
    if (idx >= KPAD_ * H_) return;
    int k  = idx >> 8;
    int jh = idx & 255;
    float4 v = make_float4(0.f, 0.f, 0.f, 0.f);
    if (k < F_) {
        v.x = Wih[(0 * H_ + jh) * F_ + k];
        v.y = Wih[(1 * H_ + jh) * F_ + k];
        v.z = Wih[(2 * H_ + jh) * F_ + k];
        v.w = Wih[(3 * H_ + jh) * F_ + k];
    } else if (k < KTOT_) {
        int kk = k - F_;
        v.x = Whh[(0 * H_ + jh) * H_ + kk];
        v.y = Whh[(1 * H_ + jh) * H_ + kk];
        v.z = Whh[(2 * H_ + jh) * H_ + kk];
        v.w = Whh[(3 * H_ + jh) * H_ + kk];
    }
    g_W[idx] = v;
    if (k == 0) {
        float4 b;
        b.x = bih[0 * H_ + jh] + bhh[0 * H_ + jh];
        b.y = bih[1 * H_ + jh] + bhh[1 * H_ + jh];
        b.z = bih[2 * H_ + jh] + bhh[2 * H_ + jh];
        b.w = bih[3 * H_ + jh] + bhh[3 * H_ + jh];
        g_bias[jh] = b;
    }
}

// One k-slice: 7 batch pairs x 4 gates = 28 FFMA2, fed by 7x LDS.64 (broadcast).
// R3/R10-proven codegen: ull-array temps with .64 loads schedule cleanly.
__device__ __forceinline__ void gemm_body(const float* __restrict__ row, float4 w,
                                          ull (&acc)[4][PAIRS_]) {
    const ull* h2 = (const ull*)row;
    ull hh[PAIRS_];
#pragma unroll
    for (int p = 0; p < PAIRS_; p++) hh[p] = h2[p];
    ull wi = splat2(w.x), wf = splat2(w.y), wg = splat2(w.z), wo = splat2(w.w);
#pragma unroll
    for (int p = 0; p < PAIRS_; p++) {
        acc[0][p] = ffma2(hh[p], wi, acc[0][p]);
        acc[1][p] = ffma2(hh[p], wf, acc[1][p]);
        acc[2][p] = ffma2(hh[p], wg, acc[2][p]);
        acc[3][p] = ffma2(hh[p], wo, acc[3][p]);
    }
}

// KN even. R10's proven 2-deep weight prefetch, linear pointer increments.
// State rows are walked linearly from Sm (weight prefetch may read up to 2 rows
// past KN in the PADDED weight array — harmless; state reads stay within KN).
template <int KN>
__device__ __forceinline__ void gemm_part(const float4* __restrict__ Wcol,
                                          const float* __restrict__ Sm,
                                          ull (&acc)[4][PAIRS_]) {
    float4 wa = Wcol[0];
    float4 wb = Wcol[H_];
    const float4* Wq = Wcol + 2 * H_;
    const float*  Sr = Sm;
#pragma unroll 1
    for (int k = 0; k < KN; k += 2) {
        float4 n0 = Wq[0];
        float4 n1 = Wq[H_];
        gemm_body(Sr, wa, acc);
        gemm_body(Sr + HSTRIDE_, wb, acc);
        wa = n0;
        wb = n1;
        Wq += 2 * H_;
        Sr += 2 * HSTRIDE_;
    }
}

// Dynamic smem layout (floats):
//   X0    [32][18]        :  576 floats   x_t double buffer 0
//   X1    [32][18]        :  576 floats   x_t double buffer 1
//   Hst   [256][18]       : 4608 floats   h state
//   Ex    [256][28] ull   : 14336 floats  (split-k partial exchange / readout scratch)
//   WfcS  [6][256]        : 1536
//   bfcS  [8], oS [84+pad]
#define SM_X0_   0
#define SM_X1_   (SM_X0_ + F_ * HSTRIDE_)
#define SM_H_    (SM_X1_ + F_ * HSTRIDE_)
#define SM_EX_   (SM_H_ + H_ * HSTRIDE_)
#define SM_WFC_  (SM_EX_ + 256 * 28 * 2)
#define SM_BFC_  (SM_WFC_ + O_ * H_)
#define SM_OS_   (SM_BFC_ + 8)
#define SM_TOTF_ (SM_OS_ + MB_ * O_ + 4)
#define SMEM_BYTES_ (SM_TOTF_ * 4)

__global__ void __launch_bounds__(NTH_, 1)
lstm_kernel(const float* __restrict__ x, const float* __restrict__ Wfc,
            const float* __restrict__ bfc, float* __restrict__ out) {
    extern __shared__ __align__(16) float smem[];
    float* X0   = smem + SM_X0_;
    float* X1   = smem + SM_X1_;
    float* Hst  = smem + SM_H_;
    ull*   Ex   = (ull*)(smem + SM_EX_);     // [jh][28]  (g*7 + p)
    float* WfcS = smem + SM_WFC_;
    float* bfcS = smem + SM_BFC_;
    float* oS   = smem + SM_OS_;

    const int tid = threadIdx.x;
    const int jh  = tid & 255;
    const int wg  = tid >> 8;        // k-half: 0 -> k[0,144), 1 -> k[144,288)
    const int b0  = blockIdx.x * MB_;

    for (int i = tid; i < H_ * HSTRIDE_; i += NTH_) Hst[i] = 0.0f;
    for (int i = tid; i < O_ * H_; i += NTH_) WfcS[i] = Wfc[i];
    if (tid < O_) bfcS[tid] = bfc[tid];

    // c state: wg0 owns pairs 0..3 (rows 0..7); wg1 pairs 4..6 (rows 8..13)
    float c[8];
#pragma unroll
    for (int r = 0; r < 8; r++) c[r] = 0.0f;

    const int pbase = wg ? 4 : 0;
    const int np    = wg ? 3 : 4;

    const float4 bias = g_bias[jh];
    // wg0: x rows (32) + h rows [0,112).  wg1: h rows [112,256).
    const float4* __restrict__ WcolX  = g_W + jh;                          // k 0..31
    const float4* __restrict__ WcolH0 = g_W + (size_t)F_ * H_ + jh;        // k 32..143
    const float4* __restrict__ WcolH1 = g_W + (size_t)KHALF_ * H_ + jh;    // k 144..287
    const float*  __restrict__ H1base = Hst + (KHALF_ - F_) * HSTRIDE_;    // h row 112

    float* Hrow  = Hst + jh * HSTRIDE_;
    ull*   ExRow = Ex + (size_t)jh * 28;

    // ---- x stager: thread slots (f, pair), 224 slots (wg0) ----
    const bool stager = tid < F_ * PAIRS_;
    int xf = 0, xp = 0;
    const float* xr0 = x;
    const float* xr1 = x;
    float xa = 0.0f, xb = 0.0f;
    if (stager) {
        xf = tid / PAIRS_;
        xp = tid - xf * PAIRS_;
        int r0 = b0 + 2 * xp;     if (r0 > B_ - 1) r0 = B_ - 1;
        int r1 = b0 + 2 * xp + 1; if (r1 > B_ - 1) r1 = B_ - 1;
        xr0 = x + (size_t)r0 * S_ * F_ + xf;
        xr1 = x + (size_t)r1 * S_ * F_ + xf;
        // Prologue: stage x_0 (full) into X0 now; prefetch ts=1 for staging x_1.
        *(ull*)(X0 + xf * HSTRIDE_ + 2 * xp) = pk(xr0[0], xr1[0]);
        xa = xr0[F_];
        xb = xr1[F_];
    }

    __syncthreads();   // H init + X0 visible

    for (int t = 0; t < STEPS_; t++) {
        float* Xcur = (t & 1) ? X1 : X0;

        // ---- look-ahead steps only: override f<6 of current x with prev output ----
        if (t >= WARM_) {
            if (stager && xf < O_) {
                *(ull*)(Xcur + xf * HSTRIDE_ + 2 * xp) =
                    pk(oS[(2 * xp) * O_ + xf], oS[(2 * xp + 1) * O_ + xf]);
            }
            __syncthreads();   // override visible (oS ordered by prev readout barrier)
        }

        // ---- split-k 4-gate GEMM (fp order identical to R10) ----
        ull acc[4][PAIRS_];
        if (wg == 0) {
            ull bi = splat2(bias.x), bf = splat2(bias.y),
                bg = splat2(bias.z), bo = splat2(bias.w);
#pragma unroll
            for (int p = 0; p < PAIRS_; p++) {
                acc[0][p] = bi; acc[1][p] = bf; acc[2][p] = bg; acc[3][p] = bo;
            }
            gemm_part<F_>(WcolX, Xcur, acc);
            gemm_part<KHALF_ - F_>(WcolH0, Hst, acc);
        } else {
            ull z = splat2(0.0f);
#pragma unroll
            for (int p = 0; p < PAIRS_; p++) {
                acc[0][p] = z; acc[1][p] = z; acc[2][p] = z; acc[3][p] = z;
            }
            gemm_part<KTOT_ - KHALF_>(WcolH1, H1base, acc);
        }

        // ---- exchange complement k-half partials ----
        if (wg == 0) {            // give pairs 4..6 to wg1
#pragma unroll
            for (int g = 0; g < 4; g++)
#pragma unroll
                for (int p = 4; p < 7; p++) ExRow[g * 7 + p] = acc[g][p];
        } else {                  // give pairs 0..3 to wg0
#pragma unroll
            for (int g = 0; g < 4; g++)
#pragma unroll
                for (int p = 0; p < 4; p++) ExRow[g * 7 + p] = acc[g][p];
        }

        // ---- stage NEXT step's x (gmem values) into the alternate buffer ----
        // Ordered for step t+1's GEMM by the h-write barrier below. la f<6 slots
        // get overwritten at the top of step t+1 (after oS is ready).
        if (stager && t + 1 < STEPS_) {
            float* Xn = ((t + 1) & 1) ? X1 : X0;
            *(ull*)(Xn + xf * HSTRIDE_ + 2 * xp) = pk(xa, xb);
            int tn2 = t + 2;
            if (tn2 < STEPS_) {
                int ts2 = (tn2 < WARM_) ? tn2 : (tn2 - WARM_);
                xa = xr0[(size_t)ts2 * F_];
                xb = xr1[(size_t)ts2 * F_];
            }
        }
        __syncthreads();   // partials + staged x visible; all S reads complete

        // ---- reduce own pairs + elementwise cell + write new h ----
#pragma unroll
        for (int q = 0; q < 4; q++) {
            if (q >= np) break;
            int p = pbase + q;
            float2 gi = unpk(add2(acc[0][p], ExRow[0 * 7 + p]));
            float2 gf = unpk(add2(acc[1][p], ExRow[1 * 7 + p]));
            float2 gg = unpk(add2(acc[2][p], ExRow[2 * 7 + p]));
            float2 go = unpk(add2(acc[3][p], ExRow[3 * 7 + p]));
            float c0 = sigf(gf.x) * c[2 * q]     + sigf(gi.x) * tanhf(gg.x);
            float c1 = sigf(gf.y) * c[2 * q + 1] + sigf(gi.y) * tanhf(gg.y);
            c[2 * q] = c0; c[2 * q + 1] = c1;
            *(ull*)(Hrow + 2 * p) = pk(sigf(go.x) * tanhf(c0),
                                       sigf(go.y) * tanhf(c1));
        }
        __syncthreads();   // new h (and staged x) complete

        // ---- STE readout: out = (h>0) @ W_fc^T + b_fc  (t = 95..127) ----
        if (t >= WARM_ - 1) {
            float* red = (float*)Ex;   // scratch [84][4] (Ex dead until next exchange)
            if (tid < MB_ * O_ * 4) {
                int slot  = tid >> 2;
                int chunk = tid & 3;
                int r  = slot / O_;
                int oi = slot - r * O_;
                const float* wrow = WfcS + oi * H_;
                float s0 = 0.0f, s1 = 0.0f;
                int jb = chunk * 64;
#pragma unroll 8
                for (int j = 0; j < 64; j += 2) {
                    s0 += (Hst[(jb + j) * HSTRIDE_ + r] > 0.0f)     ? wrow[jb + j]     : 0.0f;
                    s1 += (Hst[(jb + j + 1) * HSTRIDE_ + r] > 0.0f) ? wrow[jb + j + 1] : 0.0f;
                }
                red[slot * 4 + chunk] = s0 + s1;
            }
            __syncthreads();
            if (tid < MB_ * O_) {
                int r  = tid / O_;
                int oi = tid - r * O_;
                float a = bfcS[oi] + red[tid * 4 + 0] + red[tid * 4 + 1]
                                   + red[tid * 4 + 2] + red[tid * 4 + 3];
                oS[tid] = a;
                if (b0 + r < B_)
                    out[((size_t)(b0 + r) * (LA_ + 1) + (t - (WARM_ - 1))) * O_ + oi] = a;
            }
            __syncthreads();   // oS ready; red scratch dead before next exchange
        }
    }
}

extern "C" void kernel_launch(void* const* d_in, const int* in_sizes, int n_in,
                              void* d_out, int out_size) {
    const float* x    = (const float*)d_in[0];
    const float* W_ih = (const float*)d_in[1];
    const float* W_hh = (const float*)d_in[2];
    const float* b_ih = (const float*)d_in[3];
    const float* b_hh = (const float*)d_in[4];
    const float* W_fc = (const float*)d_in[5];
    const float* b_fc = (const float*)d_in[6];
    float* out = (float*)d_out;

    cudaFuncSetAttribute(lstm_kernel, cudaFuncAttributeMaxDynamicSharedMemorySize,
                         SMEM_BYTES_);

    pack_kernel<<<(KPAD_ * H_ + 255) / 256, 256>>>(W_ih, W_hh, b_ih, b_hh);
    lstm_kernel<<<NBLK_, NTH_, SMEM_BYTES_>>>(x, W_fc, b_fc, out);
}

// round 15
// speedup vs baseline: 1.5069x; 1.1496x over previous
#include <cuda_runtime.h>
#include <math.h>

#define B_     2048
#define S_     96
#define F_     32
#define H_     256
#define O_     6
#define LA_    32
#define WARM_  96
#define STEPS_ 128
#define MB_    14
#define PAIRS_ 7
#define NTH_   512
#define NBLK_  147        // ceil(2048 / 14); grid MUST be <= 148 (one wave)
#define KTOT_  (F_ + H_)  // 288 combined k range (x rows 0..31, h rows 32..287)
#define KHALF_ 144        // symmetric split-k per warpgroup
#define KPAD_  296        // padded weight rows: linear prefetch never OOB
#define HSTRIDE_ 18       // floats per state row: 14 data + 4 pad, 8B-aligned rows
                          // (LDS.64 only — .128 quads + 28 accs @128-reg cap => MOV blowup)

typedef unsigned long long ull;

// Static device scratch (no allocation allowed).
__device__ float4 g_W[KPAD_ * H_];   // [k][jh] -> (i,f,g,o); k<32 from Wih, 32..287 Whh
__device__ float4 g_bias[H_];        // combined bias (i,f,g,o)

// ---- packed fp32x2 helpers ----
__device__ __forceinline__ ull ffma2(ull a, ull b, ull c) {
    ull d;
    asm("fma.rn.f32x2 %0, %1, %2, %3;" : "=l"(d) : "l"(a), "l"(b), "l"(c));
    return d;
}
__device__ __forceinline__ ull add2(ull a, ull b) {
    ull d;
    asm("add.rn.f32x2 %0, %1, %2;" : "=l"(d) : "l"(a), "l"(b));
    return d;
}
__device__ __forceinline__ ull splat2(float x) {
    ull d; unsigned u = __float_as_uint(x);
    asm("mov.b64 %0, {%1, %1};" : "=l"(d) : "r"(u));
    return d;
}
__device__ __forceinline__ float2 unpk(ull v) {
    unsigned lo, hi;
    asm("mov.b64 {%0, %1}, %2;" : "=r"(lo), "=r"(hi) : "l"(v));
    return make_float2(__uint_as_float(lo), __uint_as_float(hi));
}
__device__ __forceinline__ ull pk(float a, float b) {
    ull d;
    asm("mov.b64 %0, {%1, %2};" : "=l"(d) : "r"(__float_as_uint(a)), "r"(__float_as_uint(b)));
    return d;
}
// ACCURATE activations (fast-math fails: STE chaos amplified ~1e-6 act err to 2.4e-3)
__device__ __forceinline__ float sigf(float x) { return 1.0f / (1.0f + expf(-x)); }

// One-time weight interleave: combined (x|h) k range, 4-gate float4, bias fold.
__global__ void pack_kernel(const float* __restrict__ Wih, const float* __restrict__ Whh,
                            const float* __restrict__ bih, const float* __restrict__ bhh) {
    int idx = blockIdx.x * blockDim.x + threadIdx.x;
    if (idx >= KPAD_ * H_) return;
    int k  = idx >> 8;
    int jh = idx & 255;
    float4 v = make_float4(0.f, 0.f, 0.f, 0.f);
    if (k < F_) {
        v.x = Wih[(0 * H_ + jh) * F_ + k];
        v.y = Wih[(1 * H_ + jh) * F_ + k];
        v.z = Wih[(2 * H_ + jh) * F_ + k];
        v.w = Wih[(3 * H_ + jh) * F_ + k];
    } else if (k < KTOT_) {
        int kk = k - F_;
        v.x = Whh[(0 * H_ + jh) * H_ + kk];
        v.y = Whh[(1 * H_ + jh) * H_ + kk];
        v.z = Whh[(2 * H_ + jh) * H_ + kk];
        v.w = Whh[(3 * H_ + jh) * H_ + kk];
    }
    g_W[idx] = v;
    if (k == 0) {
        float4 b;
        b.x = bih[0 * H_ + jh] + bhh[0 * H_ + jh];
        b.y = bih[1 * H_ + jh] + bhh[1 * H_ + jh];
        b.z = bih[2 * H_ + jh] + bhh[2 * H_ + jh];
        b.w = bih[3 * H_ + jh] + bhh[3 * H_ + jh];
        g_bias[jh] = b;
    }
}

// One k-slice: 7 batch pairs x 4 gates = 28 FFMA2, fed by 7x LDS.64 (broadcast).
// R3/R10-proven codegen: ull-array temps with .64 loads schedule cleanly (alu ~19%).
__device__ __forceinline__ void gemm_body(const float* __restrict__ row, float4 w,
                                          ull (&acc)[4][PAIRS_]) {
    const ull* h2 = (const ull*)row;
    ull hh[PAIRS_];
#pragma unroll
    for (int p = 0; p < PAIRS_; p++) hh[p] = h2[p];
    ull wi = splat2(w.x), wf = splat2(w.y), wg = splat2(w.z), wo = splat2(w.w);
#pragma unroll
    for (int p = 0; p < PAIRS_; p++) {
        acc[0][p] = ffma2(hh[p], wi, acc[0][p]);
        acc[1][p] = ffma2(hh[p], wf, acc[1][p]);
        acc[2][p] = ffma2(hh[p], wg, acc[2][p]);
        acc[3][p] = ffma2(hh[p], wo, acc[3][p]);
    }
}

// KN even. Linear pointer-increment 2-deep prefetch into padded weight region.
template <int KN>
__device__ __forceinline__ void gemm_part(const float4* __restrict__ Wcol,
                                          const float* __restrict__ Sm,
                                          ull (&acc)[4][PAIRS_]) {
    float4 wa = Wcol[0];
    float4 wb = Wcol[H_];
    const float4* Wq = Wcol + 2 * H_;
    const float*  Sr = Sm;
#pragma unroll 1
    for (int k = 0; k < KN; k += 2) {
        float4 n0 = Wq[0];
        float4 n1 = Wq[H_];
        gemm_body(Sr, wa, acc);
        gemm_body(Sr + HSTRIDE_, wb, acc);
        wa = n0;
        wb = n1;
        Wq += 2 * H_;
        Sr += 2 * HSTRIDE_;
    }
}

// Dynamic smem layout (floats):
//   S     [288][18]       : 5184 floats  (rows 0..31 = x_t, rows 32..287 = h)
//   Ex    [256][28] ull   : 14336 floats (split-k partial exchange / readout scratch)
//   WfcS  [6][256]        : 1536
//   bfcS  [8]
#define SM_S_    0
#define SM_EX_   (SM_S_ + KTOT_ * HSTRIDE_)
#define SM_WFC_  (SM_EX_ + 256 * 28 * 2)
#define SM_BFC_  (SM_WFC_ + O_ * H_)
#define SM_TOTF_ (SM_BFC_ + 8)
#define SMEM_BYTES_ (SM_TOTF_ * 4)

__global__ void __launch_bounds__(NTH_, 1)
lstm_kernel(const float* __restrict__ x, const float* __restrict__ Wfc,
            const float* __restrict__ bfc, float* __restrict__ out) {
    extern __shared__ __align__(16) float smem[];
    float* S    = smem + SM_S_;
    ull*   Ex   = (ull*)(smem + SM_EX_);     // [jh][28]  (g*7 + p)
    float* WfcS = smem + SM_WFC_;
    float* bfcS = smem + SM_BFC_;

    const int tid = threadIdx.x;
    const int jh  = tid & 255;
    const int wg  = tid >> 8;        // k-half: 0 -> k[0,144), 1 -> k[144,288)
    const int b0  = blockIdx.x * MB_;

    for (int i = tid; i < KTOT_ * HSTRIDE_; i += NTH_) S[i] = 0.0f;
    for (int i = tid; i < O_ * H_; i += NTH_) WfcS[i] = Wfc[i];
    if (tid < O_) bfcS[tid] = bfc[tid];

    // c state: wg0 owns pairs 0..3 (rows 0..7); wg1 pairs 4..6 (rows 8..13)
    float c[8];
#pragma unroll
    for (int r = 0; r < 8; r++) c[r] = 0.0f;

    const int pbase = wg ? 4 : 0;
    const int np    = wg ? 3 : 4;

    const float4 bias = g_bias[jh];
    const float4* __restrict__ Wcol  = g_W + (size_t)(wg * KHALF_) * H_ + jh;
    const float*  __restrict__ Sbase = S + wg * KHALF_ * HSTRIDE_;

    float* Hrow  = S + (F_ + jh) * HSTRIDE_;
    ull*   ExRow = Ex + (size_t)jh * 28;

    // ---- x stager: thread slots (f, pair), 224 slots (wg0) ----
    const bool stager = tid < F_ * PAIRS_;
    int xf = 0, xp = 0;
    const float* xr0 = x;
    const float* xr1 = x;
    float xa = 0.0f, xb = 0.0f;
    if (stager) {
        xf = tid / PAIRS_;
        xp = tid - xf * PAIRS_;
        int r0 = b0 + 2 * xp;     if (r0 > B_ - 1) r0 = B_ - 1;
        int r1 = b0 + 2 * xp + 1; if (r1 > B_ - 1) r1 = B_ - 1;
        xr0 = x + (size_t)r0 * S_ * F_ + xf;
        xr1 = x + (size_t)r1 * S_ * F_ + xf;
        // Prologue: stage x_0 into S x-rows now; prefetch ts=1 values.
        *(ull*)(S + xf * HSTRIDE_ + 2 * xp) = pk(xr0[0], xr1[0]);
        xa = xr0[F_];        // x[ts=1]
        xb = xr1[F_];
    }

    __syncthreads();   // S init + x_0 visible

    for (int t = 0; t < STEPS_; t++) {
        // ---- split-k 4-gate GEMM over this WG's 144 k-slices (R10 verbatim) ----
        ull acc[4][PAIRS_];
        if (wg == 0) {
            ull bi = splat2(bias.x), bf = splat2(bias.y),
                bg = splat2(bias.z), bo = splat2(bias.w);
#pragma unroll
            for (int p = 0; p < PAIRS_; p++) {
                acc[0][p] = bi; acc[1][p] = bf; acc[2][p] = bg; acc[3][p] = bo;
            }
        } else {
            ull z = splat2(0.0f);
#pragma unroll
            for (int p = 0; p < PAIRS_; p++) {
                acc[0][p] = z; acc[1][p] = z; acc[2][p] = z; acc[3][p] = z;
            }
        }
        gemm_part<KHALF_>(Wcol, Sbase, acc);

        // ---- exchange complement k-half partials ----
        if (wg == 0) {            // give pairs 4..6 to wg1
#pragma unroll
            for (int g = 0; g < 4; g++)
#pragma unroll
                for (int p = 4; p < 7; p++) ExRow[g * 7 + p] = acc[g][p];
        } else {                  // give pairs 0..3 to wg0
#pragma unroll
            for (int g = 0; g < 4; g++)
#pragma unroll
                for (int p = 0; p < 4; p++) ExRow[g * 7 + p] = acc[g][p];
        }

        // ---- stage x_{t+1} IN PLACE (GEMM reads of S are done; the barrier
        //      below publishes it for step t+1). For la steps, f<6 slots get
        //      overwritten by the readout's direct o-writes further down. ----
        if (stager && t + 1 < STEPS_) {
            *(ull*)(S + xf * HSTRIDE_ + 2 * xp) = pk(xa, xb);
            int tn2 = t + 2;
            if (tn2 < STEPS_) {
                int ts2 = (tn2 < WARM_) ? tn2 : (tn2 - WARM_);
                xa = xr0[(size_t)ts2 * F_];
                xb = xr1[(size_t)ts2 * F_];
            }
        }
        __syncthreads();   // partials + staged x visible; all S reads complete

        // ---- reduce own pairs + elementwise cell + write new h ----
#pragma unroll
        for (int q = 0; q < 4; q++) {
            if (q >= np) break;
            int p = pbase + q;
            float2 gi = unpk(add2(acc[0][p], ExRow[0 * 7 + p]));
            float2 gf = unpk(add2(acc[1][p], ExRow[1 * 7 + p]));
            float2 gg = unpk(add2(acc[2][p], ExRow[2 * 7 + p]));
            float2 go = unpk(add2(acc[3][p], ExRow[3 * 7 + p]));
            float c0 = sigf(gf.x) * c[2 * q]     + sigf(gi.x) * tanhf(gg.x);
            float c1 = sigf(gf.y) * c[2 * q + 1] + sigf(gi.y) * tanhf(gg.y);
            c[2 * q] = c0; c[2 * q + 1] = c1;
            *(ull*)(Hrow + 2 * p) = pk(sigf(go.x) * tanhf(c0),
                                       sigf(go.y) * tanhf(c1));
        }
        __syncthreads();   // new h complete

        // ---- STE readout: out = (h>0) @ W_fc^T + b_fc  (t = 95..127).
        //      Output also written DIRECTLY into S x-rows (f = oi < 6) for the
        //      next step's look-ahead input — replaces the old oS indirection. ----
        if (t >= WARM_ - 1) {
            float* red = (float*)Ex;   // scratch [84][4] (Ex dead until next exchange)
            const float* Hs = S + F_ * HSTRIDE_;
            if (tid < MB_ * O_ * 4) {
                int slot  = tid >> 2;
                int chunk = tid & 3;
                int r  = slot / O_;
                int oi = slot - r * O_;
                const float* wrow = WfcS + oi * H_;
                float s0 = 0.0f, s1 = 0.0f;
                int jb = chunk * 64;
#pragma unroll 8
                for (int j = 0; j < 64; j += 2) {
                    s0 += (Hs[(jb + j) * HSTRIDE_ + r] > 0.0f)     ? wrow[jb + j]     : 0.0f;
                    s1 += (Hs[(jb + j + 1) * HSTRIDE_ + r] > 0.0f) ? wrow[jb + j + 1] : 0.0f;
                }
                red[slot * 4 + chunk] = s0 + s1;
            }
            __syncthreads();
            if (tid < MB_ * O_) {
                int r  = tid / O_;
                int oi = tid - r * O_;
                float a = bfcS[oi] + red[tid * 4 + 0] + red[tid * 4 + 1]
                                   + red[tid * 4 + 2] + red[tid * 4 + 3];
                S[oi * HSTRIDE_ + r] = a;   // next step's x[:, oi] = o
                if (b0 + r < B_)
                    out[((size_t)(b0 + r) * (LA_ + 1) + (t - (WARM_ - 1))) * O_ + oi] = a;
            }
            __syncthreads();   // o-writes + red reuse ordered before next step
        }
    }
}

extern "C" void kernel_launch(void* const* d_in, const int* in_sizes, int n_in,
                              void* d_out, int out_size) {
    const float* x    = (const float*)d_in[0];
    const float* W_ih = (const float*)d_in[1];
    const float* W_hh = (const float*)d_in[2];
    const float* b_ih = (const float*)d_in[3];
    const float* b_hh = (const float*)d_in[4];
    const float* W_fc = (const float*)d_in[5];
    const float* b_fc = (const float*)d_in[6];
    float* out = (float*)d_out;

    cudaFuncSetAttribute(lstm_kernel, cudaFuncAttributeMaxDynamicSharedMemorySize,
                         SMEM_BYTES_);

    pack_kernel<<<(KPAD_ * H_ + 255) / 256, 256>>>(W_ih, W_hh, b_ih, b_hh);
    lstm_kernel<<<NBLK_, NTH_, SMEM_BYTES_>>>(x, W_fc, b_fc, out);
}

// round 16
// speedup vs baseline: 1.5157x; 1.0059x over previous
#include <cuda_runtime.h>
#include <math.h>

#define B_     2048
#define S_     96
#define F_     32
#define H_     256
#define O_     6
#define LA_    32
#define WARM_  96
#define STEPS_ 128
#define MB_    14
#define PAIRS_ 7
#define NTH_   512
#define NBLK_  147        // ceil(2048 / 14); grid MUST be <= 148 (one wave)
#define KTOT_  (F_ + H_)  // 288 combined k range (x rows 0..31, h rows 32..287)
#define KHALF_ 144        // symmetric split-k per warpgroup
#define KPAD_  296        // padded weight rows: linear prefetch never OOB
#define HSTRIDE_ 18       // floats per state row: 14 data + 4 pad, 8B-aligned rows
                          // (LDS.64 only — .128 quads + 28 accs @128-reg cap => MOV blowup)

typedef unsigned long long ull;

// Static device scratch (no allocation allowed).
__device__ float4 g_W[KPAD_ * H_];   // [k][jh] -> (i,f,g,o); k<32 from Wih, 32..287 Whh
__device__ float4 g_bias[H_];        // combined bias (i,f,g,o)

// ---- packed fp32x2 helpers ----
__device__ __forceinline__ ull ffma2(ull a, ull b, ull c) {
    ull d;
    asm("fma.rn.f32x2 %0, %1, %2, %3;" : "=l"(d) : "l"(a), "l"(b), "l"(c));
    return d;
}
__device__ __forceinline__ ull add2(ull a, ull b) {
    ull d;
    asm("add.rn.f32x2 %0, %1, %2;" : "=l"(d) : "l"(a), "l"(b));
    return d;
}
__device__ __forceinline__ ull splat2(float x) {
    ull d; unsigned u = __float_as_uint(x);
    asm("mov.b64 %0, {%1, %1};" : "=l"(d) : "r"(u));
    return d;
}
__device__ __forceinline__ float2 unpk(ull v) {
    unsigned lo, hi;
    asm("mov.b64 {%0, %1}, %2;" : "=r"(lo), "=r"(hi) : "l"(v));
    return make_float2(__uint_as_float(lo), __uint_as_float(hi));
}
__device__ __forceinline__ ull pk(float a, float b) {
    ull d;
    asm("mov.b64 %0, {%1, %2};" : "=l"(d) : "r"(__float_as_uint(a)), "r"(__float_as_uint(b)));
    return d;
}
// ACCURATE activations (fast-math fails: STE chaos amplified ~1e-6 act err to 2.4e-3).
// rcp.rn(1+e) is IEEE-correctly-rounded reciprocal == div.rn with numerator 1.0
// -> BITWISE identical to 1.0f/(1.0f+e), but guaranteed short MUFU.RCP expansion.
__device__ __forceinline__ float rcp_rn(float y) {
    float r;
    asm("rcp.rn.f32 %0, %1;" : "=f"(r) : "f"(y));
    return r;
}
__device__ __forceinline__ float sigf(float x) { return rcp_rn(1.0f + expf(-x)); }

__device__ __forceinline__ void prefetchL1(const void* p) {
    asm volatile("prefetch.global.L1 [%0];" :: "l"(p));
}

// One-time weight interleave: combined (x|h) k range, 4-gate float4, bias fold.
__global__ void pack_kernel(const float* __restrict__ Wih, const float* __restrict__ Whh,
                            const float* __restrict__ bih, const float* __restrict__ bhh) {
    int idx = blockIdx.x * blockDim.x + threadIdx.x;
    if (idx >= KPAD_ * H_) return;
    int k  = idx >> 8;
    int jh = idx & 255;
    float4 v = make_float4(0.f, 0.f, 0.f, 0.f);
    if (k < F_) {
        v.x = Wih[(0 * H_ + jh) * F_ + k];
        v.y = Wih[(1 * H_ + jh) * F_ + k];
        v.z = Wih[(2 * H_ + jh) * F_ + k];
        v.w = Wih[(3 * H_ + jh) * F_ + k];
    } else if (k < KTOT_) {
        int kk = k - F_;
        v.x = Whh[(0 * H_ + jh) * H_ + kk];
        v.y = Whh[(1 * H_ + jh) * H_ + kk];
        v.z = Whh[(2 * H_ + jh) * H_ + kk];
        v.w = Whh[(3 * H_ + jh) * H_ + kk];
    }
    g_W[idx] = v;
    if (k == 0) {
        float4 b;
        b.x = bih[0 * H_ + jh] + bhh[0 * H_ + jh];
        b.y = bih[1 * H_ + jh] + bhh[1 * H_ + jh];
        b.z = bih[2 * H_ + jh] + bhh[2 * H_ + jh];
        b.w = bih[3 * H_ + jh] + bhh[3 * H_ + jh];
        g_bias[jh] = b;
    }
}

// One k-slice: 7 batch pairs x 4 gates = 28 FFMA2, fed by 7x LDS.64 (broadcast).
// R3/R10-proven codegen: ull-array temps with .64 loads schedule cleanly (alu ~19%).
__device__ __forceinline__ void gemm_body(const float* __restrict__ row, float4 w,
                                          ull (&acc)[4][PAIRS_]) {
    const ull* h2 = (const ull*)row;
    ull hh[PAIRS_];
#pragma unroll
    for (int p = 0; p < PAIRS_; p++) hh[p] = h2[p];
    ull wi = splat2(w.x), wf = splat2(w.y), wg = splat2(w.z), wo = splat2(w.w);
#pragma unroll
    for (int p = 0; p < PAIRS_; p++) {
        acc[0][p] = ffma2(hh[p], wi, acc[0][p]);
        acc[1][p] = ffma2(hh[p], wf, acc[1][p]);
        acc[2][p] = ffma2(hh[p], wg, acc[2][p]);
        acc[3][p] = ffma2(hh[p], wo, acc[3][p]);
    }
}

// KN even. Linear pointer-increment 2-deep prefetch into padded weight region.
template <int KN>
__device__ __forceinline__ void gemm_part(const float4* __restrict__ Wcol,
                                          const float* __restrict__ Sm,
                                          ull (&acc)[4][PAIRS_]) {
    float4 wa = Wcol[0];
    float4 wb = Wcol[H_];
    const float4* Wq = Wcol + 2 * H_;
    const float*  Sr = Sm;
#pragma unroll 1
    for (int k = 0; k < KN; k += 2) {
        float4 n0 = Wq[0];
        float4 n1 = Wq[H_];
        gemm_body(Sr, wa, acc);
        gemm_body(Sr + HSTRIDE_, wb, acc);
        wa = n0;
        wb = n1;
        Wq += 2 * H_;
        Sr += 2 * HSTRIDE_;
    }
}

// Dynamic smem layout (floats):
//   S     [288][18]       : 5184 floats  (rows 0..31 = x_t, rows 32..287 = h)
//   Ex    [256][28] ull   : 14336 floats (split-k partial exchange / readout scratch)
//   WfcS  [6][256]        : 1536
//   bfcS  [8]
#define SM_S_    0
#define SM_EX_   (SM_S_ + KTOT_ * HSTRIDE_)
#define SM_WFC_  (SM_EX_ + 256 * 28 * 2)
#define SM_BFC_  (SM_WFC_ + O_ * H_)
#define SM_TOTF_ (SM_BFC_ + 8)
#define SMEM_BYTES_ (SM_TOTF_ * 4)

__global__ void __launch_bounds__(NTH_, 1)
lstm_kernel(const float* __restrict__ x, const float* __restrict__ Wfc,
            const float* __restrict__ bfc, float* __restrict__ out) {
    extern __shared__ __align__(16) float smem[];
    float* S    = smem + SM_S_;
    ull*   Ex   = (ull*)(smem + SM_EX_);     // [jh][28]  (g*7 + p)
    float* WfcS = smem + SM_WFC_;
    float* bfcS = smem + SM_BFC_;

    const int tid = threadIdx.x;
    const int jh  = tid & 255;
    const int wg  = tid >> 8;        // k-half: 0 -> k[0,144), 1 -> k[144,288)
    const int b0  = blockIdx.x * MB_;

    for (int i = tid; i < KTOT_ * HSTRIDE_; i += NTH_) S[i] = 0.0f;
    for (int i = tid; i < O_ * H_; i += NTH_) WfcS[i] = Wfc[i];
    if (tid < O_) bfcS[tid] = bfc[tid];

    // c state: wg0 owns pairs 0..3 (rows 0..7); wg1 pairs 4..6 (rows 8..13)
    float c[8];
#pragma unroll
    for (int r = 0; r < 8; r++) c[r] = 0.0f;

    const int pbase = wg ? 4 : 0;
    const int np    = wg ? 3 : 4;

    const float4 bias = g_bias[jh];
    const float4* __restrict__ Wcol  = g_W + (size_t)(wg * KHALF_) * H_ + jh;
    const float*  __restrict__ Sbase = S + wg * KHALF_ * HSTRIDE_;

    float* Hrow  = S + (F_ + jh) * HSTRIDE_;
    ull*   ExRow = Ex + (size_t)jh * 28;

    // ---- x stager: thread slots (f, pair), 224 slots (wg0) ----
    const bool stager = tid < F_ * PAIRS_;
    int xf = 0, xp = 0;
    const float* xr0 = x;
    const float* xr1 = x;
    float xa = 0.0f, xb = 0.0f;
    if (stager) {
        xf = tid / PAIRS_;
        xp = tid - xf * PAIRS_;
        int r0 = b0 + 2 * xp;     if (r0 > B_ - 1) r0 = B_ - 1;
        int r1 = b0 + 2 * xp + 1; if (r1 > B_ - 1) r1 = B_ - 1;
        xr0 = x + (size_t)r0 * S_ * F_ + xf;
        xr1 = x + (size_t)r1 * S_ * F_ + xf;
        // Prologue: stage x_0 into S x-rows now; prefetch ts=1 values.
        *(ull*)(S + xf * HSTRIDE_ + 2 * xp) = pk(xr0[0], xr1[0]);
        xa = xr0[F_];        // x[ts=1]
        xb = xr1[F_];
    }

    __syncthreads();   // S init + x_0 visible

    for (int t = 0; t < STEPS_; t++) {
        // ---- split-k 4-gate GEMM over this WG's 144 k-slices (R10 verbatim) ----
        ull acc[4][PAIRS_];
        if (wg == 0) {
            ull bi = splat2(bias.x), bf = splat2(bias.y),
                bg = splat2(bias.z), bo = splat2(bias.w);
#pragma unroll
            for (int p = 0; p < PAIRS_; p++) {
                acc[0][p] = bi; acc[1][p] = bf; acc[2][p] = bg; acc[3][p] = bo;
            }
        } else {
            ull z = splat2(0.0f);
#pragma unroll
            for (int p = 0; p < PAIRS_; p++) {
                acc[0][p] = z; acc[1][p] = z; acc[2][p] = z; acc[3][p] = z;
            }
        }
        gemm_part<KHALF_>(Wcol, Sbase, acc);

        // ---- exchange complement k-half partials ----
        if (wg == 0) {            // give pairs 4..6 to wg1
#pragma unroll
            for (int g = 0; g < 4; g++)
#pragma unroll
                for (int p = 4; p < 7; p++) ExRow[g * 7 + p] = acc[g][p];
        } else {                  // give pairs 0..3 to wg0
#pragma unroll
            for (int g = 0; g < 4; g++)
#pragma unroll
                for (int p = 0; p < 4; p++) ExRow[g * 7 + p] = acc[g][p];
        }

        // ---- stage x_{t+1} IN PLACE (GEMM reads of S are done; the barrier
        //      below publishes it for step t+1). For la steps, f<6 slots get
        //      overwritten by the readout's direct o-writes further down. ----
        if (stager && t + 1 < STEPS_) {
            *(ull*)(S + xf * HSTRIDE_ + 2 * xp) = pk(xa, xb);
            int tn2 = t + 2;
            if (tn2 < STEPS_) {
                int ts2 = (tn2 < WARM_) ? tn2 : (tn2 - WARM_);
                xa = xr0[(size_t)ts2 * F_];
                xb = xr1[(size_t)ts2 * F_];
            }
        }

        // ---- warm L1 with next step's first weight rows (GEMM + LSU idle here;
        //      post-barrier LDG then hits L1 @~39cyc instead of L2 @~250cyc) ----
        prefetchL1(Wcol);
        prefetchL1(Wcol + H_);
        prefetchL1(Wcol + 2 * H_);
        prefetchL1(Wcol + 3 * H_);

        __syncthreads();   // partials + staged x visible; all S reads complete

        // ---- reduce own pairs + elementwise cell + write new h ----
#pragma unroll
        for (int q = 0; q < 4; q++) {
            if (q >= np) break;
            int p = pbase + q;
            float2 gi = unpk(add2(acc[0][p], ExRow[0 * 7 + p]));
            float2 gf = unpk(add2(acc[1][p], ExRow[1 * 7 + p]));
            float2 gg = unpk(add2(acc[2][p], ExRow[2 * 7 + p]));
            float2 go = unpk(add2(acc[3][p], ExRow[3 * 7 + p]));
            float c0 = sigf(gf.x) * c[2 * q]     + sigf(gi.x) * tanhf(gg.x);
            float c1 = sigf(gf.y) * c[2 * q + 1] + sigf(gi.y) * tanhf(gg.y);
            c[2 * q] = c0; c[2 * q + 1] = c1;
            *(ull*)(Hrow + 2 * p) = pk(sigf(go.x) * tanhf(c0),
                                       sigf(go.y) * tanhf(c1));
        }
        __syncthreads();   // new h complete

        // ---- STE readout: out = (h>0) @ W_fc^T + b_fc  (t = 95..127).
        //      Output also written DIRECTLY into S x-rows (f = oi < 6) for the
        //      next step's look-ahead input. ----
        if (t >= WARM_ - 1) {
            float* red = (float*)Ex;   // scratch [84][4] (Ex dead until next exchange)
            const float* Hs = S + F_ * HSTRIDE_;
            if (tid < MB_ * O_ * 4) {
                int slot  = tid >> 2;
                int chunk = tid & 3;
                int r  = slot / O_;
                int oi = slot - r * O_;
                const float* wrow = WfcS + oi * H_;
                float s0 = 0.0f, s1 = 0.0f;
                int jb = chunk * 64;
#pragma unroll 8
                for (int j = 0; j < 64; j += 2) {
                    s0 += (Hs[(jb + j) * HSTRIDE_ + r] > 0.0f)     ? wrow[jb + j]     : 0.0f;
                    s1 += (Hs[(jb + j + 1) * HSTRIDE_ + r] > 0.0f) ? wrow[jb + j + 1] : 0.0f;
                }
                red[slot * 4 + chunk] = s0 + s1;
            }
            __syncthreads();
            if (tid < MB_ * O_) {
                int r  = tid / O_;
                int oi = tid - r * O_;
                float a = bfcS[oi] + red[tid * 4 + 0] + red[tid * 4 + 1]
                                   + red[tid * 4 + 2] + red[tid * 4 + 3];
                S[oi * HSTRIDE_ + r] = a;   // next step's x[:, oi] = o
                if (b0 + r < B_)
                    out[((size_t)(b0 + r) * (LA_ + 1) + (t - (WARM_ - 1))) * O_ + oi] = a;
            }
            __syncthreads();   // o-writes + red reuse ordered before next step
        }
    }
}

extern "C" void kernel_launch(void* const* d_in, const int* in_sizes, int n_in,
                              void* d_out, int out_size) {
    const float* x    = (const float*)d_in[0];
    const float* W_ih = (const float*)d_in[1];
    const float* W_hh = (const float*)d_in[2];
    const float* b_ih = (const float*)d_in[3];
    const float* b_hh = (const float*)d_in[4];
    const float* W_fc = (const float*)d_in[5];
    const float* b_fc = (const float*)d_in[6];
    float* out = (float*)d_out;

    cudaFuncSetAttribute(lstm_kernel, cudaFuncAttributeMaxDynamicSharedMemorySize,
                         SMEM_BYTES_);

    pack_kernel<<<(KPAD_ * H_ + 255) / 256, 256>>>(W_ih, W_hh, b_ih, b_hh);
    lstm_kernel<<<NBLK_, NTH_, SMEM_BYTES_>>>(x, W_fc, b_fc, out);
}